// round 2
// baseline (speedup 1.0000x reference)
#include <cuda_runtime.h>
#include <cuda_bf16.h>
#include <cstdint>

// ============================================================================
// BayesianLinear on sm_103 (base ISA only — tcgen05 is blocked by compute_103
// PTX target). Split-precision bf16 GEMM via mma.sync.m16n8k16:
//   w = mu + softplus(rho)*eps  ->  (w_hi, w_lo) bf16
//   x                           ->  (x_hi, x_lo) bf16
//   out = x_hi*w_hi + x_hi*w_lo + x_lo*w_hi  (fp32 accum)  + bias
// ============================================================================

#define IN_F   4096
#define OUT_F  4096
#define BATCH  4096

// ---------------- scratch (no cudaMalloc allowed) ----------------
__device__ __align__(16) __nv_bfloat16 g_w_hi[(size_t)OUT_F * IN_F];
__device__ __align__(16) __nv_bfloat16 g_w_lo[(size_t)OUT_F * IN_F];
__device__ __align__(16) __nv_bfloat16 g_x_hi[(size_t)BATCH * IN_F];
__device__ __align__(16) __nv_bfloat16 g_x_lo[(size_t)BATCH * IN_F];
__device__ __align__(16) float         g_bias[OUT_F];

// ---------------- helpers ----------------
__device__ __forceinline__ uint32_t smem_to_u32(const void* p) {
    uint32_t a;
    asm("{ .reg .u64 t; cvta.to.shared.u64 t, %1; cvt.u32.u64 %0, t; }" : "=r"(a) : "l"(p));
    return a;
}

__device__ __forceinline__ void cp16(uint32_t saddr, const void* gptr) {
    size_t ga = __cvta_generic_to_global(gptr);
    asm volatile("cp.async.cg.shared.global [%0], [%1], 16;"
                 :: "r"(saddr), "l"(ga) : "memory");
}
#define CP_COMMIT() asm volatile("cp.async.commit_group;" ::: "memory")
#define CP_WAIT2()  asm volatile("cp.async.wait_group 2;" ::: "memory")

__device__ __forceinline__ void ldsm_x4(uint32_t (&r)[4], uint32_t saddr) {
    asm volatile("ldmatrix.sync.aligned.m8n8.x4.shared.b16 {%0,%1,%2,%3}, [%4];"
                 : "=r"(r[0]), "=r"(r[1]), "=r"(r[2]), "=r"(r[3]) : "r"(saddr));
}

__device__ __forceinline__ void mma_bf16(float (&d)[4], const uint32_t (&a)[4],
                                         uint32_t b0, uint32_t b1) {
    asm volatile(
        "mma.sync.aligned.m16n8k16.row.col.f32.bf16.bf16.f32 "
        "{%0,%1,%2,%3}, {%4,%5,%6,%7}, {%8,%9}, {%0,%1,%2,%3};"
        : "+f"(d[0]), "+f"(d[1]), "+f"(d[2]), "+f"(d[3])
        : "r"(a[0]), "r"(a[1]), "r"(a[2]), "r"(a[3]), "r"(b0), "r"(b1));
}

__device__ __forceinline__ uint32_t pack_bf16x2(float a, float b) {
    __nv_bfloat16 ha = __float2bfloat16(a);
    __nv_bfloat16 hb = __float2bfloat16(b);
    return (uint32_t)__bfloat16_as_ushort(ha) | ((uint32_t)__bfloat16_as_ushort(hb) << 16);
}

// split fp32 -> (hi bf16, lo bf16), lo = round_bf16(x - hi)
__device__ __forceinline__ void split4(const float (&w)[4], uint2& ph, uint2& pl) {
    float hi[4], lo[4];
#pragma unroll
    for (int j = 0; j < 4; j++) {
        __nv_bfloat16 h = __float2bfloat16(w[j]);
        hi[j] = __bfloat162float(h);
        lo[j] = w[j] - hi[j];
    }
    ph = make_uint2(pack_bf16x2(hi[0], hi[1]), pack_bf16x2(hi[2], hi[3]));
    pl = make_uint2(pack_bf16x2(lo[0], lo[1]), pack_bf16x2(lo[2], lo[3]));
}

// ============================================================================
// Pass 1a: weight = mu + (log1p(exp(rho)) + 1e-8) * eps  ->  bf16 hi/lo
// ============================================================================
__global__ void __launch_bounds__(256) prep_weight_kernel(
    const float* __restrict__ mu, const float* __restrict__ rho,
    const float* __restrict__ eps)
{
    size_t i4 = (size_t)blockIdx.x * blockDim.x + threadIdx.x;
    const float4 m = ((const float4*)mu)[i4];
    const float4 r = ((const float4*)rho)[i4];
    const float4 e = ((const float4*)eps)[i4];
    float w[4];
    w[0] = m.x + (log1pf(expf(r.x)) + 1e-8f) * e.x;
    w[1] = m.y + (log1pf(expf(r.y)) + 1e-8f) * e.y;
    w[2] = m.z + (log1pf(expf(r.z)) + 1e-8f) * e.z;
    w[3] = m.w + (log1pf(expf(r.w)) + 1e-8f) * e.w;
    uint2 ph, pl;
    split4(w, ph, pl);
    ((uint2*)g_w_hi)[i4] = ph;
    ((uint2*)g_w_lo)[i4] = pl;
}

// ============================================================================
// Pass 1b: x -> bf16 hi/lo
// ============================================================================
__global__ void __launch_bounds__(256) prep_x_kernel(const float* __restrict__ x)
{
    size_t i4 = (size_t)blockIdx.x * blockDim.x + threadIdx.x;
    const float4 v = ((const float4*)x)[i4];
    float w[4] = {v.x, v.y, v.z, v.w};
    uint2 ph, pl;
    split4(w, ph, pl);
    ((uint2*)g_x_hi)[i4] = ph;
    ((uint2*)g_x_lo)[i4] = pl;
}

// ============================================================================
// Pass 1c: bias
// ============================================================================
__global__ void __launch_bounds__(256) prep_bias_kernel(
    const float* __restrict__ bmu, const float* __restrict__ brho,
    const float* __restrict__ beps)
{
    int i = blockIdx.x * blockDim.x + threadIdx.x;
    if (i < OUT_F)
        g_bias[i] = bmu[i] + (log1pf(expf(brho[i])) + 1e-8f) * beps[i];
}

// ============================================================================
// Pass 2: GEMM. CTA 128x128, BK=32 (bf16), 8 warps (2M x 4N), warp 64x32.
// 3-stage cp.async pipeline. Fragments via ldmatrix. 3 mma passes / position.
// ============================================================================
#define BM 128
#define BN 128
#define BK 32
#define KPAD 40          // bf16 elems per smem row (80 B) — conflict-free ldmatrix
#define ARR_BYTES 10240  // 128 rows * 80 B
#define OFF_AH 0
#define OFF_AL 10240
#define OFF_BH 20480
#define OFF_BL 30720
#define STAGE_BYTES 40960
#define NSTAGE 3
#define SMEM_SIZE (NSTAGE * STAGE_BYTES)

__global__ void __launch_bounds__(256, 1) gemm_kernel(float* __restrict__ out)
{
    extern __shared__ char smem[];
    const uint32_t sbase = smem_to_u32(smem);
    const int tid  = threadIdx.x;
    const int lane = tid & 31;
    const int w    = tid >> 5;
    const int wm   = w >> 2;   // 0..1
    const int wn   = w & 3;    // 0..3
    const int m0 = blockIdx.y * BM;
    const int n0 = blockIdx.x * BN;

    float acc[4][4][4];
#pragma unroll
    for (int f = 0; f < 4; f++)
#pragma unroll
        for (int n = 0; n < 4; n++)
#pragma unroll
            for (int q = 0; q < 4; q++) acc[f][n][q] = 0.0f;

    // per-thread cp.async coordinates: 2 chunks of 16B per array
    // chunk c: row = c/4 (0..127), col8 = (c%4)*8 bf16
    const int c0row = tid >> 2, c0c8 = (tid & 3) << 3;
    const int c1row = (tid + 256) >> 2, c1c8 = c0c8;

    // fragment base offsets in bf16 units (lane-dependent)
    const uint32_t a_base = (uint32_t)((wm * 64 + (lane & 15)) * KPAD + (lane >> 4) * 8);
    const uint32_t b_base = (uint32_t)((wn * 32 + (lane & 7) + ((lane >> 4) & 1) * 8) * KPAD
                                       + ((lane >> 3) & 1) * 8);

#define LOAD_STAGE(ST, KT) do {                                                   \
    uint32_t sb_ = sbase + (uint32_t)(ST) * STAGE_BYTES;                          \
    int k0_ = (KT) * BK;                                                          \
    {                                                                             \
        uint32_t so_ = (uint32_t)(c0row * 80 + c0c8 * 2);                         \
        size_t gx_ = (size_t)(m0 + c0row) * IN_F + k0_ + c0c8;                    \
        size_t gw_ = (size_t)(n0 + c0row) * IN_F + k0_ + c0c8;                    \
        cp16(sb_ + OFF_AH + so_, g_x_hi + gx_);                                   \
        cp16(sb_ + OFF_AL + so_, g_x_lo + gx_);                                   \
        cp16(sb_ + OFF_BH + so_, g_w_hi + gw_);                                   \
        cp16(sb_ + OFF_BL + so_, g_w_lo + gw_);                                   \
    }                                                                             \
    {                                                                             \
        uint32_t so_ = (uint32_t)(c1row * 80 + c1c8 * 2);                         \
        size_t gx_ = (size_t)(m0 + c1row) * IN_F + k0_ + c1c8;                    \
        size_t gw_ = (size_t)(n0 + c1row) * IN_F + k0_ + c1c8;                    \
        cp16(sb_ + OFF_AH + so_, g_x_hi + gx_);                                   \
        cp16(sb_ + OFF_AL + so_, g_x_lo + gx_);                                   \
        cp16(sb_ + OFF_BH + so_, g_w_hi + gw_);                                   \
        cp16(sb_ + OFF_BL + so_, g_w_lo + gw_);                                   \
    }                                                                             \
} while (0)

    LOAD_STAGE(0, 0); CP_COMMIT();
    LOAD_STAGE(1, 1); CP_COMMIT();

    const int NT = IN_F / BK;   // 128
    int st_load = 2, st_comp = 0;

    for (int kt = 0; kt < NT; kt++) {
        if (kt + 2 < NT) { LOAD_STAGE(st_load, kt + 2); }
        CP_COMMIT();
        st_load++; if (st_load == NSTAGE) st_load = 0;

        CP_WAIT2();
        __syncthreads();

        const uint32_t sb = sbase + (uint32_t)st_comp * STAGE_BYTES;
        st_comp++; if (st_comp == NSTAGE) st_comp = 0;

#pragma unroll
        for (int ks = 0; ks < 2; ks++) {
            uint32_t ah[4][4], al[4][4];
#pragma unroll
            for (int f = 0; f < 4; f++) {
                uint32_t ao = sb + OFF_AH + (a_base + (uint32_t)(f * 16 * KPAD + ks * 16)) * 2;
                ldsm_x4(ah[f], ao);
                ldsm_x4(al[f], ao + (OFF_AL - OFF_AH));
            }
            uint32_t bh[2][4], bl[2][4];
#pragma unroll
            for (int p = 0; p < 2; p++) {
                uint32_t bo = sb + OFF_BH + (b_base + (uint32_t)(p * 16 * KPAD + ks * 16)) * 2;
                ldsm_x4(bh[p], bo);
                ldsm_x4(bl[p], bo + (OFF_BL - OFF_BH));
            }
#pragma unroll
            for (int f = 0; f < 4; f++) {
#pragma unroll
                for (int n = 0; n < 4; n++) {
                    const int p = n >> 1, q = (n & 1) * 2;
                    mma_bf16(acc[f][n], ah[f], bh[p][q], bh[p][q + 1]);
                    mma_bf16(acc[f][n], ah[f], bl[p][q], bl[p][q + 1]);
                    mma_bf16(acc[f][n], al[f], bh[p][q], bh[p][q + 1]);
                }
            }
        }
        __syncthreads();
    }

    // ---- epilogue: D frag (m16n8): rows lane/4, lane/4+8; cols 2*(lane%4) ----
#pragma unroll
    for (int n = 0; n < 4; n++) {
        const int c = n0 + wn * 32 + n * 8 + (lane & 3) * 2;
        const float2 bs = *(const float2*)(g_bias + c);
#pragma unroll
        for (int f = 0; f < 4; f++) {
            const int r = m0 + wm * 64 + f * 16 + (lane >> 2);
            float2 v0, v1;
            v0.x = acc[f][n][0] + bs.x; v0.y = acc[f][n][1] + bs.y;
            v1.x = acc[f][n][2] + bs.x; v1.y = acc[f][n][3] + bs.y;
            *(float2*)(out + (size_t)r * OUT_F + c) = v0;
            *(float2*)(out + (size_t)(r + 8) * OUT_F + c) = v1;
        }
    }
}

// ============================================================================
// launch
// ============================================================================
extern "C" void kernel_launch(void* const* d_in, const int* in_sizes, int n_in,
                              void* d_out, int out_size)
{
    const float* x    = (const float*)d_in[0];
    const float* wmu  = (const float*)d_in[1];
    const float* wrho = (const float*)d_in[2];
    const float* bmu  = (const float*)d_in[3];
    const float* brho = (const float*)d_in[4];
    const float* weps = (const float*)d_in[5];
    const float* beps = (const float*)d_in[6];
    float* out = (float*)d_out;

    prep_weight_kernel<<<(OUT_F * (IN_F / 4)) / 256, 256>>>(wmu, wrho, weps);
    prep_x_kernel<<<(BATCH * (IN_F / 4)) / 256, 256>>>(x);
    prep_bias_kernel<<<OUT_F / 256, 256>>>(bmu, brho, beps);

    static bool attr_set = false;
    if (!attr_set) {
        cudaFuncSetAttribute(gemm_kernel, cudaFuncAttributeMaxDynamicSharedMemorySize, SMEM_SIZE);
        attr_set = true;
    }
    dim3 grid(OUT_F / BN, BATCH / BM);
    gemm_kernel<<<grid, 256, SMEM_SIZE>>>(out);
}

// round 3
// speedup vs baseline: 1.1991x; 1.1991x over previous
#include <cuda_runtime.h>
#include <cuda_bf16.h>
#include <cstdint>

// ============================================================================
// BayesianLinear on sm_103 (base ISA — tcgen05 blocked by compute_103 target).
// Split-precision bf16 GEMM via mma.sync.m16n8k16:
//   w = mu + softplus(rho)*eps  ->  (w_hi, w_lo) bf16
//   x                           ->  (x_hi, x_lo) bf16
//   out = x_hi*w_hi + x_hi*w_lo + x_lo*w_hi  (fp32 accum)  + bias
// R2 -> R3: 2 CTAs/SM (2-stage pipeline, <=128 regs) to fill tensor-pipe
// bubbles left by per-CTA barriers/waits.
// ============================================================================

#define IN_F   4096
#define OUT_F  4096
#define BATCH  4096

// ---------------- scratch (no cudaMalloc allowed) ----------------
__device__ __align__(16) __nv_bfloat16 g_w_hi[(size_t)OUT_F * IN_F];
__device__ __align__(16) __nv_bfloat16 g_w_lo[(size_t)OUT_F * IN_F];
__device__ __align__(16) __nv_bfloat16 g_x_hi[(size_t)BATCH * IN_F];
__device__ __align__(16) __nv_bfloat16 g_x_lo[(size_t)BATCH * IN_F];
__device__ __align__(16) float         g_bias[OUT_F];

// ---------------- helpers ----------------
__device__ __forceinline__ uint32_t smem_to_u32(const void* p) {
    uint32_t a;
    asm("{ .reg .u64 t; cvta.to.shared.u64 t, %1; cvt.u32.u64 %0, t; }" : "=r"(a) : "l"(p));
    return a;
}

__device__ __forceinline__ void cp16(uint32_t saddr, const void* gptr) {
    size_t ga = __cvta_generic_to_global(gptr);
    asm volatile("cp.async.cg.shared.global [%0], [%1], 16;"
                 :: "r"(saddr), "l"(ga) : "memory");
}
#define CP_COMMIT() asm volatile("cp.async.commit_group;" ::: "memory")
#define CP_WAIT1()  asm volatile("cp.async.wait_group 1;" ::: "memory")

__device__ __forceinline__ void ldsm_x4(uint32_t (&r)[4], uint32_t saddr) {
    asm volatile("ldmatrix.sync.aligned.m8n8.x4.shared.b16 {%0,%1,%2,%3}, [%4];"
                 : "=r"(r[0]), "=r"(r[1]), "=r"(r[2]), "=r"(r[3]) : "r"(saddr));
}

__device__ __forceinline__ void mma_bf16(float (&d)[4], const uint32_t (&a)[4],
                                         uint32_t b0, uint32_t b1) {
    asm volatile(
        "mma.sync.aligned.m16n8k16.row.col.f32.bf16.bf16.f32 "
        "{%0,%1,%2,%3}, {%4,%5,%6,%7}, {%8,%9}, {%0,%1,%2,%3};"
        : "+f"(d[0]), "+f"(d[1]), "+f"(d[2]), "+f"(d[3])
        : "r"(a[0]), "r"(a[1]), "r"(a[2]), "r"(a[3]), "r"(b0), "r"(b1));
}

__device__ __forceinline__ uint32_t pack_bf16x2(float a, float b) {
    __nv_bfloat16 ha = __float2bfloat16(a);
    __nv_bfloat16 hb = __float2bfloat16(b);
    return (uint32_t)__bfloat16_as_ushort(ha) | ((uint32_t)__bfloat16_as_ushort(hb) << 16);
}

// split fp32 -> (hi bf16, lo bf16), lo = round_bf16(x - hi)
__device__ __forceinline__ void split4(const float (&w)[4], uint2& ph, uint2& pl) {
    float hi[4], lo[4];
#pragma unroll
    for (int j = 0; j < 4; j++) {
        __nv_bfloat16 h = __float2bfloat16(w[j]);
        hi[j] = __bfloat162float(h);
        lo[j] = w[j] - hi[j];
    }
    ph = make_uint2(pack_bf16x2(hi[0], hi[1]), pack_bf16x2(hi[2], hi[3]));
    pl = make_uint2(pack_bf16x2(lo[0], lo[1]), pack_bf16x2(lo[2], lo[3]));
}

// ============================================================================
// Pass 1a: weight = mu + (log1p(exp(rho)) + 1e-8) * eps  ->  bf16 hi/lo
// ============================================================================
__global__ void __launch_bounds__(256) prep_weight_kernel(
    const float* __restrict__ mu, const float* __restrict__ rho,
    const float* __restrict__ eps)
{
    size_t i4 = (size_t)blockIdx.x * blockDim.x + threadIdx.x;
    const float4 m = ((const float4*)mu)[i4];
    const float4 r = ((const float4*)rho)[i4];
    const float4 e = ((const float4*)eps)[i4];
    float w[4];
    w[0] = m.x + (log1pf(expf(r.x)) + 1e-8f) * e.x;
    w[1] = m.y + (log1pf(expf(r.y)) + 1e-8f) * e.y;
    w[2] = m.z + (log1pf(expf(r.z)) + 1e-8f) * e.z;
    w[3] = m.w + (log1pf(expf(r.w)) + 1e-8f) * e.w;
    uint2 ph, pl;
    split4(w, ph, pl);
    ((uint2*)g_w_hi)[i4] = ph;
    ((uint2*)g_w_lo)[i4] = pl;
}

// ============================================================================
// Pass 1b: x -> bf16 hi/lo
// ============================================================================
__global__ void __launch_bounds__(256) prep_x_kernel(const float* __restrict__ x)
{
    size_t i4 = (size_t)blockIdx.x * blockDim.x + threadIdx.x;
    const float4 v = ((const float4*)x)[i4];
    float w[4] = {v.x, v.y, v.z, v.w};
    uint2 ph, pl;
    split4(w, ph, pl);
    ((uint2*)g_x_hi)[i4] = ph;
    ((uint2*)g_x_lo)[i4] = pl;
}

// ============================================================================
// Pass 1c: bias
// ============================================================================
__global__ void __launch_bounds__(256) prep_bias_kernel(
    const float* __restrict__ bmu, const float* __restrict__ brho,
    const float* __restrict__ beps)
{
    int i = blockIdx.x * blockDim.x + threadIdx.x;
    if (i < OUT_F)
        g_bias[i] = bmu[i] + (log1pf(expf(brho[i])) + 1e-8f) * beps[i];
}

// ============================================================================
// Pass 2: GEMM. CTA 128x128, BK=32 (bf16), 8 warps (2M x 4N), warp 64x32.
// 2-stage cp.async pipeline, 2 CTAs/SM. Fragments via ldmatrix.
// ============================================================================
#define BM 128
#define BN 128
#define BK 32
#define KPAD 40          // bf16 elems per smem row (80 B) — conflict-free ldmatrix
#define OFF_AH 0
#define OFF_AL 10240
#define OFF_BH 20480
#define OFF_BL 30720
#define STAGE_BYTES 40960
#define NSTAGE 2
#define SMEM_SIZE (NSTAGE * STAGE_BYTES)

__global__ void __launch_bounds__(256, 2) gemm_kernel(float* __restrict__ out)
{
    extern __shared__ char smem[];
    const uint32_t sbase = smem_to_u32(smem);
    const int tid  = threadIdx.x;
    const int lane = tid & 31;
    const int w    = tid >> 5;
    const int wm   = w >> 2;   // 0..1
    const int wn   = w & 3;    // 0..3
    const int m0 = blockIdx.y * BM;
    const int n0 = blockIdx.x * BN;

    float acc[4][4][4];
#pragma unroll
    for (int f = 0; f < 4; f++)
#pragma unroll
        for (int n = 0; n < 4; n++)
#pragma unroll
            for (int q = 0; q < 4; q++) acc[f][n][q] = 0.0f;

    // per-thread cp.async coordinates: 2 chunks of 16B per array
    const int c0row = tid >> 2, c0c8 = (tid & 3) << 3;
    const int c1row = (tid + 256) >> 2, c1c8 = c0c8;

    // fragment base offsets in bf16 units (lane-dependent)
    const uint32_t a_base = (uint32_t)((wm * 64 + (lane & 15)) * KPAD + (lane >> 4) * 8);
    const uint32_t b_base = (uint32_t)((wn * 32 + (lane & 7) + ((lane >> 4) & 1) * 8) * KPAD
                                       + ((lane >> 3) & 1) * 8);

#define LOAD_STAGE(ST, KT) do {                                                   \
    uint32_t sb_ = sbase + (uint32_t)(ST) * STAGE_BYTES;                          \
    int k0_ = (KT) * BK;                                                          \
    {                                                                             \
        uint32_t so_ = (uint32_t)(c0row * 80 + c0c8 * 2);                         \
        size_t gx_ = (size_t)(m0 + c0row) * IN_F + k0_ + c0c8;                    \
        size_t gw_ = (size_t)(n0 + c0row) * IN_F + k0_ + c0c8;                    \
        cp16(sb_ + OFF_AH + so_, g_x_hi + gx_);                                   \
        cp16(sb_ + OFF_AL + so_, g_x_lo + gx_);                                   \
        cp16(sb_ + OFF_BH + so_, g_w_hi + gw_);                                   \
        cp16(sb_ + OFF_BL + so_, g_w_lo + gw_);                                   \
    }                                                                             \
    {                                                                             \
        uint32_t so_ = (uint32_t)(c1row * 80 + c1c8 * 2);                         \
        size_t gx_ = (size_t)(m0 + c1row) * IN_F + k0_ + c1c8;                    \
        size_t gw_ = (size_t)(n0 + c1row) * IN_F + k0_ + c1c8;                    \
        cp16(sb_ + OFF_AH + so_, g_x_hi + gx_);                                   \
        cp16(sb_ + OFF_AL + so_, g_x_lo + gx_);                                   \
        cp16(sb_ + OFF_BH + so_, g_w_hi + gw_);                                   \
        cp16(sb_ + OFF_BL + so_, g_w_lo + gw_);                                   \
    }                                                                             \
} while (0)

    LOAD_STAGE(0, 0); CP_COMMIT();
    LOAD_STAGE(1, 1); CP_COMMIT();

    const int NT = IN_F / BK;   // 128

    for (int kt = 0; kt < NT; kt++) {
        CP_WAIT1();            // stage (kt & 1) ready
        __syncthreads();

        const uint32_t sb = sbase + (uint32_t)(kt & 1) * STAGE_BYTES;

#pragma unroll
        for (int ks = 0; ks < 2; ks++) {
            // B fragments for this k16 slice (hi + lo): 16 regs
            uint32_t bh[2][4], bl[2][4];
#pragma unroll
            for (int p = 0; p < 2; p++) {
                uint32_t bo = sb + OFF_BH + (b_base + (uint32_t)(p * 16 * KPAD + ks * 16)) * 2;
                ldsm_x4(bh[p], bo);
                ldsm_x4(bl[p], bo + (OFF_BL - OFF_BH));
            }
            // A fragments staged per-f: 8 live regs
#pragma unroll
            for (int f = 0; f < 4; f++) {
                uint32_t ah[4], al[4];
                uint32_t ao = sb + OFF_AH + (a_base + (uint32_t)(f * 16 * KPAD + ks * 16)) * 2;
                ldsm_x4(ah, ao);
                ldsm_x4(al, ao + (OFF_AL - OFF_AH));
#pragma unroll
                for (int n = 0; n < 4; n++) {
                    const int p = n >> 1, q = (n & 1) * 2;
                    mma_bf16(acc[f][n], ah, bh[p][q], bh[p][q + 1]);
                    mma_bf16(acc[f][n], ah, bl[p][q], bl[p][q + 1]);
                    mma_bf16(acc[f][n], al, bh[p][q], bh[p][q + 1]);
                }
            }
        }
        __syncthreads();       // all warps done reading stage (kt & 1)

        if (kt + 2 < NT) LOAD_STAGE(kt & 1, kt + 2);
        CP_COMMIT();           // keep group count consistent even when empty
    }

    // ---- epilogue: D frag (m16n8): rows lane/4, lane/4+8; cols 2*(lane%4) ----
#pragma unroll
    for (int n = 0; n < 4; n++) {
        const int c = n0 + wn * 32 + n * 8 + (lane & 3) * 2;
        const float2 bs = *(const float2*)(g_bias + c);
#pragma unroll
        for (int f = 0; f < 4; f++) {
            const int r = m0 + wm * 64 + f * 16 + (lane >> 2);
            float2 v0, v1;
            v0.x = acc[f][n][0] + bs.x; v0.y = acc[f][n][1] + bs.y;
            v1.x = acc[f][n][2] + bs.x; v1.y = acc[f][n][3] + bs.y;
            *(float2*)(out + (size_t)r * OUT_F + c) = v0;
            *(float2*)(out + (size_t)(r + 8) * OUT_F + c) = v1;
        }
    }
}

// ============================================================================
// launch
// ============================================================================
extern "C" void kernel_launch(void* const* d_in, const int* in_sizes, int n_in,
                              void* d_out, int out_size)
{
    const float* x    = (const float*)d_in[0];
    const float* wmu  = (const float*)d_in[1];
    const float* wrho = (const float*)d_in[2];
    const float* bmu  = (const float*)d_in[3];
    const float* brho = (const float*)d_in[4];
    const float* weps = (const float*)d_in[5];
    const float* beps = (const float*)d_in[6];
    float* out = (float*)d_out;

    prep_weight_kernel<<<(OUT_F * (IN_F / 4)) / 256, 256>>>(wmu, wrho, weps);
    prep_x_kernel<<<(BATCH * (IN_F / 4)) / 256, 256>>>(x);
    prep_bias_kernel<<<OUT_F / 256, 256>>>(bmu, brho, beps);

    static bool attr_set = false;
    if (!attr_set) {
        cudaFuncSetAttribute(gemm_kernel, cudaFuncAttributeMaxDynamicSharedMemorySize, SMEM_SIZE);
        attr_set = true;
    }
    dim3 grid(OUT_F / BN, BATCH / BM);
    gemm_kernel<<<grid, 256, SMEM_SIZE>>>(out);
}